// round 15
// baseline (speedup 1.0000x reference)
#include <cuda_runtime.h>
#include <math.h>

#define Bsz 32
#define Ssz 512
#define Esz 256
#define HDz 256
#define Hsz 512
#define Lsz 32
#define NG  1024   // 4*HD gate rows per direction
#define RP  129    // red pitch

// ------------------- scratch -------------------
__device__ float g_x0[Bsz * Ssz * Esz];                 // embed out
__device__ float g_gx[2 * Bsz * Ssz * NG];              // gate preacts, both dirs
__device__ float g_h0[Bsz * Ssz * Hsz];                 // layer0 out
__device__ float g_h1[Bsz * Ssz * Hsz];                 // layer1 out

// ------------------- packed f32x2 helpers -------------------
__device__ __forceinline__ void dfma2(unsigned long long& d, unsigned long long a,
                                      unsigned long long b) {
    asm("fma.rn.f32x2 %0, %1, %2, %0;" : "+l"(d) : "l"(a), "l"(b));
}
__device__ __forceinline__ float2 up2(unsigned long long v) {
    float2 f;
    asm("mov.b64 {%0, %1}, %2;" : "=f"(f.x), "=f"(f.y) : "l"(v));
    return f;
}
__device__ __forceinline__ unsigned long long dupf(float b) {
    unsigned long long r;
    asm("mov.b64 %0, {%1, %1};" : "=l"(r) : "f"(b));
    return r;
}
__device__ __forceinline__ unsigned smem_u32(const void* p) {
    unsigned a;
    asm("{ .reg .u64 t; cvta.to.shared.u64 t, %1; cvt.u32.u64 %0, t; }"
        : "=r"(a) : "l"(p));
    return a;
}
__device__ __forceinline__ unsigned mapa32(unsigned addr, unsigned rank) {
    unsigned r;
    asm("mapa.shared::cluster.u32 %0, %1, %2;" : "=r"(r) : "r"(addr), "r"(rank));
    return r;
}
__device__ __forceinline__ void wait_par_acq_cluster(unsigned mbar, unsigned parity) {
    asm volatile(
        "{\n\t.reg .pred P;\n"
        "W%=:\n\t"
        "mbarrier.try_wait.parity.acquire.cluster.shared::cta.b64 P, [%0], %1, 0x989680;\n\t"
        "@P bra D%=;\n\t"
        "bra W%=;\n"
        "D%=:\n\t}"
        :: "r"(mbar), "r"(parity) : "memory");
}
__device__ __forceinline__ void arrive_release_cluster(unsigned mbar) {
    asm volatile("mbarrier.arrive.release.cluster.shared::cluster.b64 _, [%0];"
                 :: "r"(mbar) : "memory");
}
__device__ __forceinline__ float4 ld_cluster_v4(unsigned addr) {
    float4 v;
    asm volatile("ld.shared::cluster.v4.f32 {%0, %1, %2, %3}, [%4];"
                 : "=f"(v.x), "=f"(v.y), "=f"(v.z), "=f"(v.w) : "r"(addr) : "memory");
    return v;
}

// ------------------- embed -------------------
__global__ void k_embed(const int* __restrict__ x, const float* __restrict__ emb,
                        float* __restrict__ out) {
    int row = blockIdx.x;
    int t = threadIdx.x;               // 64 threads
    int tok = x[row];
    const float4* s = (const float4*)(emb + (size_t)tok * Esz);
    ((float4*)(out + (size_t)row * Esz))[t] = s[t];
}

// ------------------- GEMM (R8 champion): C = A @ W^T + b1 + b2, BK=8 -------------------
__global__ __launch_bounds__(256) void k_gemm(const float* __restrict__ A,
                                              const float* __restrict__ W,
                                              const float* __restrict__ b1,
                                              const float* __restrict__ b2,
                                              const int* __restrict__ xlen,
                                              float* __restrict__ C,
                                              int K, int N) {
    int m0 = blockIdx.y * 128, n0 = blockIdx.x * 128;
    {
        int b = m0 >> 9;
        int s0 = m0 & 511;
        if (s0 >= xlen[b]) return;     // rows only ever read masked
    }
    __shared__ __align__(16) float As[8][132];
    __shared__ __align__(16) float Bs[8][132];
    int tid = threadIdx.x;
    int tx = tid & 15, ty = tid >> 4;
    int lr = tid >> 1;
    int lk = (tid & 1) * 4;
    const float* Ap = A + (size_t)(m0 + lr) * K + lk;
    const float* Wp = W + (size_t)(n0 + lr) * K + lk;

    unsigned long long acc[4][8];
#pragma unroll
    for (int i = 0; i < 4; i++)
#pragma unroll
        for (int j = 0; j < 8; j++) acc[i][j] = 0ull;

    float4 av = *(const float4*)(Ap);
    float4 bv = *(const float4*)(Wp);

    for (int k0 = 0; k0 < K; k0 += 8) {
        __syncthreads();
        As[lk + 0][lr] = av.x; As[lk + 1][lr] = av.y;
        As[lk + 2][lr] = av.z; As[lk + 3][lr] = av.w;
        Bs[lk + 0][lr] = bv.x; Bs[lk + 1][lr] = bv.y;
        Bs[lk + 2][lr] = bv.z; Bs[lk + 3][lr] = bv.w;
        __syncthreads();
        float4 av_n = av, bv_n = bv;
        if (k0 + 8 < K) {
            av_n = *(const float4*)(Ap + k0 + 8);
            bv_n = *(const float4*)(Wp + k0 + 8);
        }
#pragma unroll
        for (int kk = 0; kk < 8; kk++) {
            ulonglong2 A0 = *(const ulonglong2*)&As[kk][ty * 4];
            ulonglong2 A1 = *(const ulonglong2*)&As[kk][64 + ty * 4];
            float4 q0 = *(const float4*)&Bs[kk][tx * 4];
            float4 q1 = *(const float4*)&Bs[kk][64 + tx * 4];
            unsigned long long am[4] = {A0.x, A0.y, A1.x, A1.y};
            unsigned long long bd[8] = {dupf(q0.x), dupf(q0.y), dupf(q0.z), dupf(q0.w),
                                        dupf(q1.x), dupf(q1.y), dupf(q1.z), dupf(q1.w)};
#pragma unroll
            for (int mp = 0; mp < 4; mp++)
#pragma unroll
                for (int j = 0; j < 8; j++) dfma2(acc[mp][j], am[mp], bd[j]);
        }
        av = av_n; bv = bv_n;
    }

#pragma unroll
    for (int mp = 0; mp < 4; mp++) {
        int r = m0 + ((mp < 2) ? ty * 4 + 2 * mp : 64 + ty * 4 + 2 * (mp - 2));
#pragma unroll
        for (int j = 0; j < 8; j++) {
            int c = n0 + ((j < 4) ? 4 * tx + j : 64 + 4 * tx + (j - 4));
            float2 f = up2(acc[mp][j]);
            float bb = b1[c] + b2[c];
            C[(size_t)r * N + c]       = f.x + bb;
            C[(size_t)(r + 1) * N + c] = f.y + bb;
        }
    }
}

__device__ __forceinline__ float sigm(float x) { return 1.f / (1.f + expf(-x)); }

// ------------------- BiLSTM recurrence: 16-warp FMA + PULL exchange -------------
// grid (8, 16): x = unit-slice (cluster dim 8), y = dir*8 + bgroup. 512 threads.
// FMA thread (warp w, lane l): kq = w&3 (k-quarter), col c = (w>>2)*32 + l.
// Cell thread t<128: b = t&3, ul = t>>2. Stage threads t<256: one v4 pull each.
__global__ __launch_bounds__(512, 1) __cluster_dims__(8, 1, 1)
void k_recur(const float* __restrict__ gx, const float* __restrict__ w_hh,
             const int* __restrict__ xlen, float* __restrict__ hout) {
    __shared__ __align__(16) float hstage[1024];    // FMA source, [b][256 units]
    __shared__ __align__(16) float own_h[2 * 128];  // producer slots [slot][b][32]
    __shared__ __align__(16) float red[16 * RP];    // [kq*4+b][col]
    __shared__ __align__(8) unsigned long long mbars[2];

    unsigned mb_full = smem_u32(mbars);
    unsigned own_u32 = smem_u32(own_h);

    int us  = blockIdx.x;
    int dir = blockIdx.y >> 3;
    int bg  = blockIdx.y & 7;
    int U0 = us * 32, B0 = bg * 4;
    int t = threadIdx.x;
    int w = t >> 5, l = t & 31;
    int kq = w & 3;
    int c  = (w >> 2) * 32 + l;
    int kbase = kq * 64;

    const float* wd  = w_hh + (size_t)dir * NG * HDz;
    const float* gxd = gx + (size_t)dir * ((size_t)Bsz * Ssz * NG);

    if (t == 0) {
        asm volatile("mbarrier.init.shared.b64 [%0], 8;" :: "r"(mb_full) : "memory");
        asm volatile("mbarrier.init.shared.b64 [%0], 8;" :: "r"(mb_full + 8) : "memory");
    }
    for (int idx = t; idx < 1024; idx += 512) hstage[idx] = 0.f;   // step-0 h = 0

    // W slice into registers: wreg[j] = packed {w[c][kbase+2j], w[c][kbase+2j+1]}
    unsigned long long wreg[32];
    {
        int gr = (c & 3) * 256 + U0 + (c >> 2);
        const unsigned long long* wrow =
            (const unsigned long long*)(wd + (size_t)gr * HDz + kbase);
#pragma unroll
        for (int j = 0; j < 32; j++) wreg[j] = wrow[j];
    }

    // cluster-wide step count (identical in all 8 CTAs of this cluster)
    int nsteps = max(max(xlen[B0], xlen[B0 + 1]), max(xlen[B0 + 2], xlen[B0 + 3]));

    // cell-thread state
    int cb = t & 3, cul = t >> 2;          // valid for t<128
    int clen = (t < 128) ? xlen[B0 + cb] : 0;
    float cst = 0.f, hst = 0.f;

    // stage-thread mapping (t<256): pulls 4 units of one batch from one peer
    int sgb  = t >> 6;              // batch 0..3 (for t<256)
    int spos = (t & 63) * 4;        // unit 0..252
    int srk  = spos >> 5;           // source rank
    int slo  = spos & 31;           // unit offset within source CTA

    __syncthreads();
    asm volatile("barrier.cluster.arrive.aligned;" ::: "memory");
    asm volatile("barrier.cluster.wait.aligned;" ::: "memory");

    unsigned src_base = 0;
    if (t < 256)
        src_base = mapa32(own_u32, (unsigned)srk) + (unsigned)((sgb * 32 + slo) * 4);
    unsigned my_arrive_mbar = (t < 8) ? mapa32(mb_full, (unsigned)t) : 0;

    int u0cnt = 0, u1cnt = 0;

    for (int step = 0; step < nsteps; step++) {
        int si = step & 1;
        int sn = si ^ 1;

        // prefetch gx for cell threads (independent of h exchange -> before wait)
        float gxi = 0.f, gxf = 0.f, gxg = 0.f, gxo = 0.f;
        if (t < 128) {
            int s_b = step;
            if (dir) s_b = (step < clen) ? (clen - 1 - step) : step;
            const float* gp = gxd + ((size_t)(B0 + cb) * Ssz + s_b) * NG + U0 + cul;
            gxi = __ldg(gp);
            gxf = __ldg(gp + 256);
            gxg = __ldg(gp + 512);
            gxo = __ldg(gp + 768);
        }

        if (step >= 1 && t < 256) {
            int par;
            if (si) { par = u1cnt & 1; u1cnt++; }
            else    { par = u0cnt & 1; u0cnt++; }
            wait_par_acq_cluster(mb_full + si * 8, (unsigned)par);
            // pull h(step) from all peers' own_h[si] into hstage
            float4 v = ld_cluster_v4(src_base + (unsigned)(si * 512));
            *(float4*)&hstage[sgb * 256 + spos] = v;
        }
        __syncthreads();                      // hstage complete

        // FMA: acc_b = sum_k w[c][k] * h[b][k], k in [kbase, kbase+64)
        const float* hb = hstage + kbase;
        unsigned long long a0 = 0, a1 = 0, a2 = 0, a3 = 0;
#pragma unroll
        for (int j = 0; j < 16; j++) {
            ulonglong2 h0 = *(const ulonglong2*)(hb + 4 * j);
            ulonglong2 h1 = *(const ulonglong2*)(hb + 256 + 4 * j);
            ulonglong2 h2 = *(const ulonglong2*)(hb + 512 + 4 * j);
            ulonglong2 h3 = *(const ulonglong2*)(hb + 768 + 4 * j);
            dfma2(a0, wreg[2 * j], h0.x); dfma2(a0, wreg[2 * j + 1], h0.y);
            dfma2(a1, wreg[2 * j], h1.x); dfma2(a1, wreg[2 * j + 1], h1.y);
            dfma2(a2, wreg[2 * j], h2.x); dfma2(a2, wreg[2 * j + 1], h2.y);
            dfma2(a3, wreg[2 * j], h3.x); dfma2(a3, wreg[2 * j + 1], h3.y);
        }
        float2 f;
        f = up2(a0); red[(kq * 4 + 0) * RP + c] = f.x + f.y;
        f = up2(a1); red[(kq * 4 + 1) * RP + c] = f.x + f.y;
        f = up2(a2); red[(kq * 4 + 2) * RP + c] = f.x + f.y;
        f = up2(a3); red[(kq * 4 + 3) * RP + c] = f.x + f.y;
        __syncthreads();                      // red complete, hstage reads retired

        if (t < 128) {
            int ci = cul * 4;
            float gi = gxi, gf = gxf, gg = gxg, go = gxo;
#pragma unroll
            for (int q = 0; q < 4; q++) {
                const float* rr = red + (q * 4 + cb) * RP + ci;
                gi += rr[0]; gf += rr[1]; gg += rr[2]; go += rr[3];
            }

            float iv = sigm(gi), fv = sigm(gf), gv = tanhf(gg), ov = sigm(go);
            float cn = fv * cst + iv * gv;
            float hn = ov * tanhf(cn);
            bool m = step < clen;
            cst = m ? cn : cst;
            hst = m ? hn : hst;
            float outv = m ? hn : 0.f;

            // store own h(step+1) locally; peers pull it next step
            own_h[sn * 128 + cb * 32 + cul] = hst;

            int pos, oc;
            if (!dir) { pos = step; oc = U0 + cul; }
            else {
                pos = m ? (clen - 1 - step) : step;
                oc = 256 + U0 + cul;
            }
            hout[((size_t)(B0 + cb) * Ssz + pos) * Hsz + oc] = outv;
        }
        __syncthreads();   // drains own_h STS; red reads done

        if (step < nsteps - 1 && t < 8) {
            arrive_release_cluster(my_arrive_mbar + sn * 8);
        }
    }
}

// ------------------- emissions: out[M,32] = h[M,512] @ dw[32,512]^T + db -------------------
__global__ __launch_bounds__(256) void k_emis(const float* __restrict__ h,
                                              const float* __restrict__ dw,
                                              const float* __restrict__ db,
                                              float* __restrict__ out) {
    __shared__ float wT[128 * 33];
    __shared__ float hs[32 * 128];
    int tid = threadIdx.x;
    int w = tid >> 5, j = tid & 31;
    int row0 = blockIdx.x * 32;
    float acc[4] = {0.f, 0.f, 0.f, 0.f};
    for (int kc = 0; kc < 4; kc++) {
        __syncthreads();
        for (int idx = tid; idx < 4096; idx += 256) {
            int jj = idx >> 7, k = idx & 127;
            wT[k * 33 + jj] = dw[(size_t)jj * 512 + kc * 128 + k];
        }
        for (int idx = tid; idx < 4096; idx += 256) {
            int r = idx >> 7, k = idx & 127;
            hs[r * 128 + k] = h[(size_t)(row0 + r) * 512 + kc * 128 + k];
        }
        __syncthreads();
#pragma unroll 4
        for (int k = 0; k < 128; k++) {
            float wv = wT[k * 33 + j];
#pragma unroll
            for (int i = 0; i < 4; i++) acc[i] += hs[(w * 4 + i) * 128 + k] * wv;
        }
    }
    float bias = db[j];
#pragma unroll
    for (int i = 0; i < 4; i++)
        out[(size_t)(row0 + w * 4 + i) * 32 + j] = acc[i] + bias;
}

// ------------------- Viterbi: 32 blocks x 32 threads -------------------
__global__ void k_viterbi(const float* __restrict__ em, const int* __restrict__ xlen,
                          const float* __restrict__ trans, const float* __restrict__ st,
                          const float* __restrict__ et,
                          float* __restrict__ tags_out, float* __restrict__ scores_out) {
    __shared__ unsigned char bp[512][32];
    int b = blockIdx.x, j = threadIdx.x;
    int len = xlen[b];
    float tc[32];
#pragma unroll
    for (int i = 0; i < 32; i++) tc[i] = trans[i * 32 + j];
    const float* e = em + (size_t)b * Ssz * Lsz;
    float alpha = st[j] + e[j];
    for (int t = 1; t < 512; t++) {
        if (t < len) {
            float best = -1e30f; int arg = 0;
#pragma unroll
            for (int i = 0; i < 32; i++) {
                float ai = __shfl_sync(0xffffffffu, alpha, i);
                float cand = ai + tc[i];
                if (cand > best) { best = cand; arg = i; }
            }
            alpha = best + e[(size_t)t * 32 + j];
            bp[t][j] = (unsigned char)arg;
        } else {
            bp[t][j] = (unsigned char)j;
        }
    }
    __syncwarp();
    float fin = alpha + et[j];
    float bv = fin; int bi = j;
#pragma unroll
    for (int off = 16; off; off >>= 1) {
        float ovv = __shfl_down_sync(0xffffffffu, bv, off);
        int oi = __shfl_down_sync(0xffffffffu, bi, off);
        if (ovv > bv || (ovv == bv && oi < bi)) { bv = ovv; bi = oi; }
    }
    if (j == 0) {
        scores_out[b] = bv;
        int tg = bi;
        for (int t = 511; t >= 1; t--) {
            tags_out[(size_t)b * Ssz + t] = (t < len) ? (float)tg : 0.f;
            tg = bp[t][tg];
        }
        tags_out[(size_t)b * Ssz] = (float)tg;
    }
}

// ------------------- launch -------------------
extern "C" void kernel_launch(void* const* d_in, const int* in_sizes, int n_in,
                              void* d_out, int out_size) {
    const int*   x       = (const int*)d_in[0];
    const int*   xlen    = (const int*)d_in[1];
    const float* emb     = (const float*)d_in[2];
    const float* w_ih_l0 = (const float*)d_in[3];
    const float* w_hh_l0 = (const float*)d_in[4];
    const float* b_ih_l0 = (const float*)d_in[5];
    const float* b_hh_l0 = (const float*)d_in[6];
    const float* w_ih_l1 = (const float*)d_in[7];
    const float* w_hh_l1 = (const float*)d_in[8];
    const float* b_ih_l1 = (const float*)d_in[9];
    const float* b_hh_l1 = (const float*)d_in[10];
    const float* dw      = (const float*)d_in[11];
    const float* db      = (const float*)d_in[12];
    const float* trans   = (const float*)d_in[13];
    const float* strn    = (const float*)d_in[14];
    const float* etrn    = (const float*)d_in[15];
    float* out = (float*)d_out;

    float *x0, *gx, *h0, *h1;
    cudaGetSymbolAddress((void**)&x0, g_x0);
    cudaGetSymbolAddress((void**)&gx, g_gx);
    cudaGetSymbolAddress((void**)&h0, g_h0);
    cudaGetSymbolAddress((void**)&h1, g_h1);

    const size_t GXD = (size_t)Bsz * Ssz * NG;
    const size_t HBYTES = (size_t)Bsz * Ssz * Hsz * sizeof(float);

    // zero padded tails of h buffers (positions >= nsteps never written)
    cudaMemsetAsync(h0, 0, HBYTES);
    cudaMemsetAsync(h1, 0, HBYTES);

    k_embed<<<Bsz * Ssz, 64>>>(x, emb, x0);

    // layer 0: K=256
    k_gemm<<<dim3(8, 128), 256>>>(x0, w_ih_l0,            b_ih_l0,      b_hh_l0,      xlen, gx,       256, NG);
    k_gemm<<<dim3(8, 128), 256>>>(x0, w_ih_l0 + NG * 256, b_ih_l0 + NG, b_hh_l0 + NG, xlen, gx + GXD, 256, NG);
    k_recur<<<dim3(8, 16), 512>>>(gx, w_hh_l0, xlen, h0);

    // layer 1: K=512
    k_gemm<<<dim3(8, 128), 256>>>(h0, w_ih_l1,            b_ih_l1,      b_hh_l1,      xlen, gx,       512, NG);
    k_gemm<<<dim3(8, 128), 256>>>(h0, w_ih_l1 + NG * 512, b_ih_l1 + NG, b_hh_l1 + NG, xlen, gx + GXD, 512, NG);
    k_recur<<<dim3(8, 16), 512>>>(gx, w_hh_l1, xlen, h1);

    k_emis<<<512, 256>>>(h1, dw, db, out);

    float* tags   = out + (size_t)Bsz * Ssz * Lsz;
    float* scores = tags + (size_t)Bsz * Ssz;
    k_viterbi<<<Bsz, 32>>>(out, xlen, trans, strn, etrn, tags, scores);
}

// round 17
// speedup vs baseline: 1.2257x; 1.2257x over previous
#include <cuda_runtime.h>
#include <cuda_bf16.h>
#include <math.h>

#define Bsz 32
#define Ssz 512
#define Esz 256
#define HDz 256
#define Hsz 512
#define Lsz 32
#define NG  1024   // 4*HD gate rows per direction
#define RP  129    // red pitch (recurrence)
#define GP  40     // gemm smem pitch in bf16 (80B rows: 16B-aligned, conflict-free)

// ------------------- scratch -------------------
__device__ float g_x0[Bsz * Ssz * Esz];                 // embed out
__device__ float g_gx[2 * Bsz * Ssz * NG];              // gate preacts, both dirs
__device__ float g_h0[Bsz * Ssz * Hsz];                 // layer0 out
__device__ float g_h1[Bsz * Ssz * Hsz];                 // layer1 out
__device__ __nv_bfloat16 g_ahi[Bsz * Ssz * Hsz];        // activation hi (max K=512)
__device__ __nv_bfloat16 g_alo[Bsz * Ssz * Hsz];        // activation lo
__device__ __nv_bfloat16 g_whi[2 * NG * Hsz];           // weight hi (max K=512)
__device__ __nv_bfloat16 g_wlo[2 * NG * Hsz];           // weight lo

// ------------------- packed f32x2 / misc helpers -------------------
__device__ __forceinline__ void dfma2(unsigned long long& d, unsigned long long a,
                                      unsigned long long b) {
    asm("fma.rn.f32x2 %0, %1, %2, %0;" : "+l"(d) : "l"(a), "l"(b));
}
__device__ __forceinline__ float2 up2(unsigned long long v) {
    float2 f;
    asm("mov.b64 {%0, %1}, %2;" : "=f"(f.x), "=f"(f.y) : "l"(v));
    return f;
}
__device__ __forceinline__ unsigned long long packf2(float lo, float hi) {
    unsigned long long r;
    asm("mov.b64 %0, {%1, %2};" : "=l"(r) : "f"(lo), "f"(hi));
    return r;
}
__device__ __forceinline__ unsigned smem_u32(const void* p) {
    unsigned a;
    asm("{ .reg .u64 t; cvta.to.shared.u64 t, %1; cvt.u32.u64 %0, t; }"
        : "=r"(a) : "l"(p));
    return a;
}
__device__ __forceinline__ unsigned mapa32(unsigned addr, unsigned rank) {
    unsigned r;
    asm("mapa.shared::cluster.u32 %0, %1, %2;" : "=r"(r) : "r"(addr), "r"(rank));
    return r;
}
__device__ __forceinline__ void wait_par_acq_cluster(unsigned mbar, unsigned parity) {
    asm volatile(
        "{\n\t.reg .pred P;\n"
        "W%=:\n\t"
        "mbarrier.try_wait.parity.acquire.cluster.shared::cta.b64 P, [%0], %1, 0x989680;\n\t"
        "@P bra D%=;\n\t"
        "bra W%=;\n"
        "D%=:\n\t}"
        :: "r"(mbar), "r"(parity) : "memory");
}
__device__ __forceinline__ void st_async_f64(unsigned dst, unsigned long long v,
                                             unsigned mbar) {
    asm volatile(
        "st.async.shared::cluster.mbarrier::complete_tx::bytes.b64 [%0], %1, [%2];"
        :: "r"(dst), "l"(v), "r"(mbar) : "memory");
}
// warp MMA: D += A(bf16) * B(bf16), m16n8k16, row.col, fp32 acc
__device__ __forceinline__ void mma16816(float* d, const unsigned* a,
                                         unsigned b0, unsigned b1) {
    asm volatile(
        "mma.sync.aligned.m16n8k16.row.col.f32.bf16.bf16.f32 "
        "{%0,%1,%2,%3}, {%4,%5,%6,%7}, {%8,%9}, {%0,%1,%2,%3};"
        : "+f"(d[0]), "+f"(d[1]), "+f"(d[2]), "+f"(d[3])
        : "r"(a[0]), "r"(a[1]), "r"(a[2]), "r"(a[3]), "r"(b0), "r"(b1));
}

// ------------------- embed -------------------
__global__ void k_embed(const int* __restrict__ x, const float* __restrict__ emb,
                        float* __restrict__ out) {
    int row = blockIdx.x;
    int t = threadIdx.x;               // 64 threads
    int tok = x[row];
    const float4* s = (const float4*)(emb + (size_t)tok * Esz);
    ((float4*)(out + (size_t)row * Esz))[t] = s[t];
}

// ------------------- fp32 -> bf16 hi/lo split (4 elems/thread) -------------------
__global__ void k_split(const float* __restrict__ s, __nv_bfloat16* __restrict__ hi,
                        __nv_bfloat16* __restrict__ lo) {
    int i = (blockIdx.x * 256 + threadIdx.x) * 4;
    float4 v = *(const float4*)(s + i);
    float vv[4] = {v.x, v.y, v.z, v.w};
    unsigned short hb[4], lb[4];
#pragma unroll
    for (int j = 0; j < 4; j++) {
        __nv_bfloat16 h = __float2bfloat16(vv[j]);
        __nv_bfloat16 l = __float2bfloat16(vv[j] - __bfloat162float(h));
        hb[j] = __bfloat16_as_ushort(h);
        lb[j] = __bfloat16_as_ushort(l);
    }
    *(uint2*)(hi + i) = make_uint2(((unsigned)hb[1] << 16) | hb[0],
                                   ((unsigned)hb[3] << 16) | hb[2]);
    *(uint2*)(lo + i) = make_uint2(((unsigned)lb[1] << 16) | lb[0],
                                   ((unsigned)lb[3] << 16) | lb[2]);
}

// ------------------- tensor GEMM via mma.sync: C = A@W^T + b1 + b2 (split-bf16) ---
// tile 128x128, BK=32, 256 threads (8 warps, 4m x 2n; warp tile 32x64)
__global__ __launch_bounds__(256) void k_gemm_mma(
    const __nv_bfloat16* __restrict__ Ahi, const __nv_bfloat16* __restrict__ Alo,
    const __nv_bfloat16* __restrict__ Whi, const __nv_bfloat16* __restrict__ Wlo,
    const float* __restrict__ b1, const float* __restrict__ b2,
    const int* __restrict__ xlen, float* __restrict__ C, int K, int N) {
    int m0 = blockIdx.y * 128, n0 = blockIdx.x * 128;
    { int b = m0 >> 9, s0 = m0 & 511; if (s0 >= xlen[b]) return; }

    __shared__ __align__(16) __nv_bfloat16 sAh[128 * GP];
    __shared__ __align__(16) __nv_bfloat16 sAl[128 * GP];
    __shared__ __align__(16) __nv_bfloat16 sWh[128 * GP];
    __shared__ __align__(16) __nv_bfloat16 sWl[128 * GP];

    int tid = threadIdx.x, wid = tid >> 5, lane = tid & 31;
    int laneg = lane >> 2, lane4 = lane & 3;
    int wm = wid >> 1, wn = wid & 1;
    int r0 = wm * 32, c0 = wn * 64;

    float acc[2][8][4];
#pragma unroll
    for (int i = 0; i < 2; i++)
#pragma unroll
        for (int j = 0; j < 8; j++)
#pragma unroll
            for (int q = 0; q < 4; q++) acc[i][j][q] = 0.f;

    for (int k0 = 0; k0 < K; k0 += 32) {
        __syncthreads();
        for (int idx = tid; idx < 512; idx += 256) {
            int row = idx >> 2, cq = (idx & 3) * 8;
            size_t ga = (size_t)(m0 + row) * K + k0 + cq;
            *(uint4*)&sAh[row * GP + cq] = *(const uint4*)(Ahi + ga);
            *(uint4*)&sAl[row * GP + cq] = *(const uint4*)(Alo + ga);
            size_t gw = (size_t)(n0 + row) * K + k0 + cq;
            *(uint4*)&sWh[row * GP + cq] = *(const uint4*)(Whi + gw);
            *(uint4*)&sWl[row * GP + cq] = *(const uint4*)(Wlo + gw);
        }
        __syncthreads();

#pragma unroll
        for (int kh = 0; kh < 32; kh += 16) {
            unsigned ah[2][4], al[2][4];
#pragma unroll
            for (int mt = 0; mt < 2; mt++) {
                int ar = (r0 + mt * 16 + laneg) * GP + kh + lane4 * 2;
                ah[mt][0] = *(const unsigned*)&sAh[ar];
                ah[mt][1] = *(const unsigned*)&sAh[ar + 8 * GP];
                ah[mt][2] = *(const unsigned*)&sAh[ar + 8];
                ah[mt][3] = *(const unsigned*)&sAh[ar + 8 * GP + 8];
                al[mt][0] = *(const unsigned*)&sAl[ar];
                al[mt][1] = *(const unsigned*)&sAl[ar + 8 * GP];
                al[mt][2] = *(const unsigned*)&sAl[ar + 8];
                al[mt][3] = *(const unsigned*)&sAl[ar + 8 * GP + 8];
            }
#pragma unroll
            for (int nt = 0; nt < 8; nt++) {
                int br = (c0 + nt * 8 + laneg) * GP + kh + lane4 * 2;
                unsigned bh0 = *(const unsigned*)&sWh[br];
                unsigned bh1 = *(const unsigned*)&sWh[br + 8];
                unsigned bl0 = *(const unsigned*)&sWl[br];
                unsigned bl1 = *(const unsigned*)&sWl[br + 8];
#pragma unroll
                for (int mt = 0; mt < 2; mt++) {
                    mma16816(acc[mt][nt], ah[mt], bh0, bh1);
                    mma16816(acc[mt][nt], ah[mt], bl0, bl1);
                    mma16816(acc[mt][nt], al[mt], bh0, bh1);
                }
            }
        }
    }

    // epilogue
#pragma unroll
    for (int mt = 0; mt < 2; mt++) {
        int m = m0 + r0 + mt * 16 + laneg;
#pragma unroll
        for (int nt = 0; nt < 8; nt++) {
            int n = n0 + c0 + nt * 8 + lane4 * 2;
            float bb0 = b1[n] + b2[n];
            float bb1 = b1[n + 1] + b2[n + 1];
            *(float2*)&C[(size_t)m * N + n] =
                make_float2(acc[mt][nt][0] + bb0, acc[mt][nt][1] + bb1);
            *(float2*)&C[(size_t)(m + 8) * N + n] =
                make_float2(acc[mt][nt][2] + bb0, acc[mt][nt][3] + bb1);
        }
    }
}

__device__ __forceinline__ float sigm(float x) { return 1.f / (1.f + expf(-x)); }

// ------------------- BiLSTM recurrence (R14 champion, unchanged) -----------------
__global__ __launch_bounds__(512, 1) __cluster_dims__(8, 1, 1)
void k_recur(const float* __restrict__ gx, const float* __restrict__ w_hh,
             const int* __restrict__ xlen, float* __restrict__ hout) {
    __shared__ __align__(16) float hbuf[2048];      // 2 slots x [b][256]
    __shared__ __align__(16) float red[16 * RP];    // [kq*4+b][col]
    __shared__ __align__(8) unsigned long long mbars[2];

    unsigned mb_full = smem_u32(mbars);
    unsigned hb_u32  = smem_u32(hbuf);

    int us  = blockIdx.x;
    int dir = blockIdx.y >> 3;
    int bg  = blockIdx.y & 7;
    int U0 = us * 32, B0 = bg * 4;
    int t = threadIdx.x;
    int w = t >> 5, l = t & 31;
    int kq = w & 3;
    int c  = (w >> 2) * 32 + l;
    int kbase = kq * 64;

    const float* wd  = w_hh + (size_t)dir * NG * HDz;
    const float* gxd = gx + (size_t)dir * ((size_t)Bsz * Ssz * NG);

    if (t == 0) {
        asm volatile("mbarrier.init.shared.b64 [%0], 1;" :: "r"(mb_full) : "memory");
        asm volatile("mbarrier.init.shared.b64 [%0], 1;" :: "r"(mb_full + 8) : "memory");
    }
    for (int idx = t; idx < 1024; idx += 512) hbuf[idx] = 0.f;

    unsigned long long wreg[32];
    {
        int gr = (c & 3) * 256 + U0 + (c >> 2);
        const unsigned long long* wrow =
            (const unsigned long long*)(wd + (size_t)gr * HDz + kbase);
#pragma unroll
        for (int j = 0; j < 32; j++) wreg[j] = wrow[j];
    }

    int nsteps = max(max(xlen[B0], xlen[B0 + 1]), max(xlen[B0 + 2], xlen[B0 + 3]));

    int cb = t & 3, cul = t >> 2;          // valid for t<128
    int clen = (t < 128) ? xlen[B0 + cb] : 0;
    float cst = 0.f, hst = 0.f;

    __syncthreads();
    asm volatile("barrier.cluster.arrive.aligned;" ::: "memory");
    asm volatile("barrier.cluster.wait.aligned;" ::: "memory");

    unsigned peer_hb[8], peer_full[8];
#pragma unroll
    for (int r = 0; r < 8; r++) {
        peer_hb[r]   = mapa32(hb_u32, r);
        peer_full[r] = mapa32(mb_full, r);
    }

    int u0cnt = 0, u1cnt = 0;

    for (int step = 0; step < nsteps; step++) {
        int si = step & 1;
        int so = si ^ 1;

        float gxi = 0.f, gxf = 0.f, gxg = 0.f, gxo = 0.f;
        if (t < 128) {
            int s_b = step;
            if (dir) s_b = (step < clen) ? (clen - 1 - step) : step;
            const float* gp = gxd + ((size_t)(B0 + cb) * Ssz + s_b) * NG + U0 + cul;
            gxi = __ldg(gp);
            gxf = __ldg(gp + 256);
            gxg = __ldg(gp + 512);
            gxo = __ldg(gp + 768);
        }

        if (step >= 1) {
            int par;
            if (si) { par = u1cnt & 1; u1cnt++; }
            else    { par = u0cnt & 1; u0cnt++; }
            wait_par_acq_cluster(mb_full + si * 8, (unsigned)par);
        }
        if (step < nsteps - 1 && t == 0) {
            asm volatile(
                "mbarrier.arrive.expect_tx.release.cluster.shared::cta.b64 _, [%0], %1;"
                :: "r"(mb_full + so * 8), "r"(4096u) : "memory");
        }

        const float* hb = hbuf + si * 1024 + kbase;
        unsigned long long a0 = 0, a1 = 0, a2 = 0, a3 = 0;
#pragma unroll
        for (int j = 0; j < 16; j++) {
            ulonglong2 h0 = *(const ulonglong2*)(hb + 4 * j);
            ulonglong2 h1 = *(const ulonglong2*)(hb + 256 + 4 * j);
            ulonglong2 h2 = *(const ulonglong2*)(hb + 512 + 4 * j);
            ulonglong2 h3 = *(const ulonglong2*)(hb + 768 + 4 * j);
            dfma2(a0, wreg[2 * j], h0.x); dfma2(a0, wreg[2 * j + 1], h0.y);
            dfma2(a1, wreg[2 * j], h1.x); dfma2(a1, wreg[2 * j + 1], h1.y);
            dfma2(a2, wreg[2 * j], h2.x); dfma2(a2, wreg[2 * j + 1], h2.y);
            dfma2(a3, wreg[2 * j], h3.x); dfma2(a3, wreg[2 * j + 1], h3.y);
        }
        float2 f;
        f = up2(a0); red[(kq * 4 + 0) * RP + c] = f.x + f.y;
        f = up2(a1); red[(kq * 4 + 1) * RP + c] = f.x + f.y;
        f = up2(a2); red[(kq * 4 + 2) * RP + c] = f.x + f.y;
        f = up2(a3); red[(kq * 4 + 3) * RP + c] = f.x + f.y;
        __syncthreads();

        if (t < 128) {
            int ci = cul * 4;
            float gi = gxi, gf = gxf, gg = gxg, go = gxo;
#pragma unroll
            for (int q = 0; q < 4; q++) {
                const float* rr = red + (q * 4 + cb) * RP + ci;
                gi += rr[0]; gf += rr[1]; gg += rr[2]; go += rr[3];
            }

            float iv = sigm(gi), fv = sigm(gf), gv = tanhf(gg), ov = sigm(go);
            float cn = fv * cst + iv * gv;
            float hn = ov * tanhf(cn);
            bool m = step < clen;
            cst = m ? cn : cst;
            hst = m ? hn : hst;
            float outv = m ? hn : 0.f;

            float hpart = __shfl_xor_sync(0xffffffffu, hst, 4);
            if ((t & 4) == 0 && step < nsteps - 1) {
                unsigned long long pk = packf2(hst, hpart);
                unsigned off = (unsigned)((so << 10) + cb * 256 + U0 + cul) * 4u;
#pragma unroll
                for (int r = 0; r < 8; r++)
                    st_async_f64(peer_hb[r] + off, pk, peer_full[r] + so * 8);
            }

            int pos, oc;
            if (!dir) { pos = step; oc = U0 + cul; }
            else {
                pos = m ? (clen - 1 - step) : step;
                oc = 256 + U0 + cul;
            }
            hout[((size_t)(B0 + cb) * Ssz + pos) * Hsz + oc] = outv;
        }
    }
}

// ------------------- emissions: out[M,32] = h[M,512] @ dw[32,512]^T + db -------------------
__global__ __launch_bounds__(256) void k_emis(const float* __restrict__ h,
                                              const float* __restrict__ dw,
                                              const float* __restrict__ db,
                                              float* __restrict__ out) {
    __shared__ float wT[128 * 33];
    __shared__ float hs[32 * 128];
    int tid = threadIdx.x;
    int w = tid >> 5, j = tid & 31;
    int row0 = blockIdx.x * 32;
    float acc[4] = {0.f, 0.f, 0.f, 0.f};
    for (int kc = 0; kc < 4; kc++) {
        __syncthreads();
        for (int idx = tid; idx < 4096; idx += 256) {
            int jj = idx >> 7, k = idx & 127;
            wT[k * 33 + jj] = dw[(size_t)jj * 512 + kc * 128 + k];
        }
        for (int idx = tid; idx < 4096; idx += 256) {
            int r = idx >> 7, k = idx & 127;
            hs[r * 128 + k] = h[(size_t)(row0 + r) * 512 + kc * 128 + k];
        }
        __syncthreads();
#pragma unroll 4
        for (int k = 0; k < 128; k++) {
            float wv = wT[k * 33 + j];
#pragma unroll
            for (int i = 0; i < 4; i++) acc[i] += hs[(w * 4 + i) * 128 + k] * wv;
        }
    }
    float bias = db[j];
#pragma unroll
    for (int i = 0; i < 4; i++)
        out[(size_t)(row0 + w * 4 + i) * 32 + j] = acc[i] + bias;
}

// ------------------- Viterbi: 32 blocks x 32 threads -------------------
__global__ void k_viterbi(const float* __restrict__ em, const int* __restrict__ xlen,
                          const float* __restrict__ trans, const float* __restrict__ st,
                          const float* __restrict__ et,
                          float* __restrict__ tags_out, float* __restrict__ scores_out) {
    __shared__ unsigned char bp[512][32];
    int b = blockIdx.x, j = threadIdx.x;
    int len = xlen[b];
    float tc[32];
#pragma unroll
    for (int i = 0; i < 32; i++) tc[i] = trans[i * 32 + j];
    const float* e = em + (size_t)b * Ssz * Lsz;
    float alpha = st[j] + e[j];
    for (int t = 1; t < 512; t++) {
        if (t < len) {
            float best = -1e30f; int arg = 0;
#pragma unroll
            for (int i = 0; i < 32; i++) {
                float ai = __shfl_sync(0xffffffffu, alpha, i);
                float cand = ai + tc[i];
                if (cand > best) { best = cand; arg = i; }
            }
            alpha = best + e[(size_t)t * 32 + j];
            bp[t][j] = (unsigned char)arg;
        } else {
            bp[t][j] = (unsigned char)j;
        }
    }
    __syncwarp();
    float fin = alpha + et[j];
    float bv = fin; int bi = j;
#pragma unroll
    for (int off = 16; off; off >>= 1) {
        float ovv = __shfl_down_sync(0xffffffffu, bv, off);
        int oi = __shfl_down_sync(0xffffffffu, bi, off);
        if (ovv > bv || (ovv == bv && oi < bi)) { bv = ovv; bi = oi; }
    }
    if (j == 0) {
        scores_out[b] = bv;
        int tg = bi;
        for (int t = 511; t >= 1; t--) {
            tags_out[(size_t)b * Ssz + t] = (t < len) ? (float)tg : 0.f;
            tg = bp[t][tg];
        }
        tags_out[(size_t)b * Ssz] = (float)tg;
    }
}

// ------------------- launch -------------------
extern "C" void kernel_launch(void* const* d_in, const int* in_sizes, int n_in,
                              void* d_out, int out_size) {
    const int*   x       = (const int*)d_in[0];
    const int*   xlen    = (const int*)d_in[1];
    const float* emb     = (const float*)d_in[2];
    const float* w_ih_l0 = (const float*)d_in[3];
    const float* w_hh_l0 = (const float*)d_in[4];
    const float* b_ih_l0 = (const float*)d_in[5];
    const float* b_hh_l0 = (const float*)d_in[6];
    const float* w_ih_l1 = (const float*)d_in[7];
    const float* w_hh_l1 = (const float*)d_in[8];
    const float* b_ih_l1 = (const float*)d_in[9];
    const float* b_hh_l1 = (const float*)d_in[10];
    const float* dw      = (const float*)d_in[11];
    const float* db      = (const float*)d_in[12];
    const float* trans   = (const float*)d_in[13];
    const float* strn    = (const float*)d_in[14];
    const float* etrn    = (const float*)d_in[15];
    float* out = (float*)d_out;

    float *x0, *gx, *h0, *h1;
    __nv_bfloat16 *ahi, *alo, *whi, *wlo;
    cudaGetSymbolAddress((void**)&x0, g_x0);
    cudaGetSymbolAddress((void**)&gx, g_gx);
    cudaGetSymbolAddress((void**)&h0, g_h0);
    cudaGetSymbolAddress((void**)&h1, g_h1);
    cudaGetSymbolAddress((void**)&ahi, g_ahi);
    cudaGetSymbolAddress((void**)&alo, g_alo);
    cudaGetSymbolAddress((void**)&whi, g_whi);
    cudaGetSymbolAddress((void**)&wlo, g_wlo);

    const size_t GXD = (size_t)Bsz * Ssz * NG;
    const size_t HBYTES = (size_t)Bsz * Ssz * Hsz * sizeof(float);

    cudaMemsetAsync(h0, 0, HBYTES);
    cudaMemsetAsync(h1, 0, HBYTES);

    k_embed<<<Bsz * Ssz, 64>>>(x, emb, x0);

    // ---- layer 0: split + mma GEMMs (K=256) ----
    k_split<<<(Bsz * Ssz * Esz) / 1024, 256>>>(x0, ahi, alo);
    k_split<<<(2 * NG * 256) / 1024, 256>>>(w_ih_l0, whi, wlo);
    k_gemm_mma<<<dim3(8, 128), 256>>>(ahi, alo, whi, wlo,
                                      b_ih_l0, b_hh_l0, xlen, gx, 256, NG);
    k_gemm_mma<<<dim3(8, 128), 256>>>(ahi, alo, whi + NG * 256, wlo + NG * 256,
                                      b_ih_l0 + NG, b_hh_l0 + NG, xlen, gx + GXD, 256, NG);
    k_recur<<<dim3(8, 16), 512>>>(gx, w_hh_l0, xlen, h0);

    // ---- layer 1: split + mma GEMMs (K=512) ----
    k_split<<<(Bsz * Ssz * Hsz) / 1024, 256>>>(h0, ahi, alo);
    k_split<<<(2 * NG * 512) / 1024, 256>>>(w_ih_l1, whi, wlo);
    k_gemm_mma<<<dim3(8, 128), 256>>>(ahi, alo, whi, wlo,
                                      b_ih_l1, b_hh_l1, xlen, gx, 512, NG);
    k_gemm_mma<<<dim3(8, 128), 256>>>(ahi, alo, whi + NG * 512, wlo + NG * 512,
                                      b_ih_l1 + NG, b_hh_l1 + NG, xlen, gx + GXD, 512, NG);
    k_recur<<<dim3(8, 16), 512>>>(gx, w_hh_l1, xlen, h1);

    k_emis<<<512, 256>>>(h1, dw, db, out);

    float* tags   = out + (size_t)Bsz * Ssz * Lsz;
    float* scores = tags + (size_t)Bsz * Ssz;
    k_viterbi<<<Bsz, 32>>>(out, xlen, trans, strn, etrn, tags, scores);
}